// round 5
// baseline (speedup 1.0000x reference)
#include <cuda_runtime.h>
#include <stdint.h>

// Ragged node-batch -> batch reconstruction, t-major output-streaming design.
// Inputs: src [L,NB], memory_bank [L,NB,D], lengths [NB], recover [NB]
// Output (flat): src_out [MAX_LEN,B], mb_out [MAX_LEN,B,D], hidden [B,D], lengths_out [B]
// Instance: B=32, N=64, L=128, D=256, NB=2048, MAX_LEN=8192.

#define MAXB   32
#define MAXN   64
#define TC     32            // t-rows per main block
#define MAIN_T 512           // threads per main block

// scratch map: map[t*B + b] = source row index in mb (p*NB + nb), or -1.
__device__ int g_map[1 << 20];   // 4 MB, >> 256K needed

// ---------------------------------------------------------------------------
// Setup: per-batch prefix sums -> map table, src_out, lengths_out, hidden=0.
// grid = 64 blocks, each owns MAX_LEN/64 t's for all B batches.
// ---------------------------------------------------------------------------
__global__ void __launch_bounds__(256)
setup_kernel(const float* __restrict__ src,
             const int* __restrict__ lengths,
             const int* __restrict__ recover,
             int* __restrict__ map,
             float* __restrict__ src_out,
             float* __restrict__ hidden,
             float* __restrict__ lengths_out,
             int B, int N, int NB, int MAX_LEN)
{
    const int tid = threadIdx.x;
    const int tpb = MAX_LEN / gridDim.x;      // t's per block
    const int t0  = blockIdx.x * tpb;

    __shared__ int s_incl[MAXB][MAXN];        // inclusive prefix per batch
    __shared__ int s_rc[MAXB * MAXN];

    for (int i = tid; i < B * N; i += blockDim.x) {
        s_incl[i >> 6][i & 63] = lengths[i];  // N==64
        s_rc[i] = recover[i];
    }
    __syncthreads();
    if (tid < B) {
        int s = 0;
        #pragma unroll 8
        for (int i = 0; i < MAXN; ++i) { s += s_incl[tid][i]; s_incl[tid][i] = s; }
    }
    __syncthreads();

    // fill map + src_out for my t range (coalesced: e = t*B + b linear)
    const int total = tpb * B;
    for (int k = tid; k < total; k += blockDim.x) {
        const int t = t0 + k / B;
        const int b = k - (k / B) * B;
        const int len_b = s_incl[b][MAXN - 1];
        int m = -1;
        float sval = 1.0f;
        if (t < len_b) {
            int lo = 0, hi = N;
            while (lo < hi) {
                int mid = (lo + hi) >> 1;
                if (s_incl[b][mid] > t) hi = mid; else lo = mid + 1;
            }
            const int n   = lo;
            const int off = (n > 0) ? s_incl[b][n - 1] : 0;
            const int p   = t - off;
            m = p * NB + b * N + n;
            sval = src[(size_t)p * NB + s_rc[b * N + n]];
        }
        map[(size_t)t * B + b] = m;
        src_out[(size_t)t * B + b] = sval;
    }

    if (blockIdx.x == 0) {
        // zero hidden (B*D floats)
        const int n4 = (B * 256) / 4;
        float4* h4 = reinterpret_cast<float4*>(hidden);
        for (int i = tid; i < n4; i += blockDim.x)
            h4[i] = make_float4(0.f, 0.f, 0.f, 0.f);
        if (tid < B)
            lengths_out[tid] = (float)s_incl[tid][MAXN - 1];
    }
}

// ---------------------------------------------------------------------------
// Main: gather scattered source rows, emit contiguous 32KB t-rows, fused
// hidden accumulation. Block = TC t's; thread covers 4 (b,lane) slots.
// ---------------------------------------------------------------------------
__global__ void __launch_bounds__(MAIN_T)
stream_kernel(const float* __restrict__ mb,
              const int* __restrict__ map,
              const float* __restrict__ lengths_out,
              float* __restrict__ mb_out,
              float* __restrict__ hidden,
              int B, int NB, int MAX_LEN)
{
    const int tid = threadIdx.x;
    const int t0  = blockIdx.x * TC;
    const int LANES = 64;                       // D/4
    const int rowF4 = B * LANES;                // 2048 float4 per t-row
    // chunk c: pos = c*MAIN_T + tid -> (b, lane)
    const int bA = (0 * MAIN_T + tid) >> 6, lA = tid & 63;
    const int bB = (1 * MAIN_T + tid) >> 6;
    const int bC = (2 * MAIN_T + tid) >> 6;
    const int bD = (3 * MAIN_T + tid) >> 6;

    __shared__ int   s_map[TC * MAXB];
    __shared__ float s_inv[MAXB];

    for (int i = tid; i < TC * B; i += MAIN_T) {
        int t = t0 + i / B;
        s_map[i] = (t < MAX_LEN) ? map[(size_t)t0 * B + i] : -1;
    }
    if (tid < B) {
        float lb = lengths_out[tid];
        s_inv[tid] = (lb > 0.f) ? (1.0f / lb) : 0.f;
    }
    __syncthreads();

    const float4* __restrict__ mb4 = reinterpret_cast<const float4*>(mb);
    float4* __restrict__ out4 =
        reinterpret_cast<float4*>(mb_out) + (size_t)t0 * rowF4;

    float4 acc0 = make_float4(0,0,0,0), acc1 = acc0, acc2 = acc0, acc3 = acc0;
    const float4 z4 = make_float4(0,0,0,0);

    const int tmax = min(TC, MAX_LEN - t0);
    #pragma unroll 2
    for (int tt = 0; tt < tmax; ++tt) {
        const int* mrow = s_map + tt * B;
        const int m0 = mrow[bA];
        const int m1 = mrow[bB];
        const int m2 = mrow[bC];
        const int m3 = mrow[bD];
        float4 v0 = (m0 >= 0) ? mb4[(size_t)m0 * LANES + lA] : z4;
        float4 v1 = (m1 >= 0) ? mb4[(size_t)m1 * LANES + lA] : z4;
        float4 v2 = (m2 >= 0) ? mb4[(size_t)m2 * LANES + lA] : z4;
        float4 v3 = (m3 >= 0) ? mb4[(size_t)m3 * LANES + lA] : z4;
        float4* orow = out4 + (size_t)tt * rowF4 + tid;
        orow[0 * MAIN_T] = v0;
        orow[1 * MAIN_T] = v1;
        orow[2 * MAIN_T] = v2;
        orow[3 * MAIN_T] = v3;
        acc0.x += v0.x; acc0.y += v0.y; acc0.z += v0.z; acc0.w += v0.w;
        acc1.x += v1.x; acc1.y += v1.y; acc1.z += v1.z; acc1.w += v1.w;
        acc2.x += v2.x; acc2.y += v2.y; acc2.z += v2.z; acc2.w += v2.w;
        acc3.x += v3.x; acc3.y += v3.y; acc3.z += v3.z; acc3.w += v3.w;
    }

    // hidden reduction: scale and vector-reduce (red.global.add.v4.f32)
    {
        float i0 = s_inv[bA], i1 = s_inv[bB], i2 = s_inv[bC], i3 = s_inv[bD];
        float* h0 = hidden + bA * 256 + lA * 4;
        float* h1 = hidden + bB * 256 + lA * 4;
        float* h2 = hidden + bC * 256 + lA * 4;
        float* h3 = hidden + bD * 256 + lA * 4;
        asm volatile("red.global.add.v4.f32 [%0], {%1,%2,%3,%4};" ::
            "l"(h0), "f"(acc0.x * i0), "f"(acc0.y * i0), "f"(acc0.z * i0), "f"(acc0.w * i0) : "memory");
        asm volatile("red.global.add.v4.f32 [%0], {%1,%2,%3,%4};" ::
            "l"(h1), "f"(acc1.x * i1), "f"(acc1.y * i1), "f"(acc1.z * i1), "f"(acc1.w * i1) : "memory");
        asm volatile("red.global.add.v4.f32 [%0], {%1,%2,%3,%4};" ::
            "l"(h2), "f"(acc2.x * i2), "f"(acc2.y * i2), "f"(acc2.z * i2), "f"(acc2.w * i2) : "memory");
        asm volatile("red.global.add.v4.f32 [%0], {%1,%2,%3,%4};" ::
            "l"(h3), "f"(acc3.x * i3), "f"(acc3.y * i3), "f"(acc3.z * i3), "f"(acc3.w * i3) : "memory");
    }
}

extern "C" void kernel_launch(void* const* d_in, const int* in_sizes, int n_in,
                              void* d_out, int out_size)
{
    const float* src     = (const float*)d_in[0];
    const float* mb      = (const float*)d_in[1];
    const int*   lengths = (const int*)d_in[2];
    const int*   recover = (const int*)d_in[3];

    const long long NB = in_sizes[2];
    const long long L  = in_sizes[0] / NB;
    const long long D  = in_sizes[1] / in_sizes[0];
    const long long B  = (long long)out_size / (D + 1) - NB * L;
    const long long N  = NB / B;
    const long long MAX_LEN = N * L;

    float* out = (float*)d_out;
    float* src_out     = out;
    float* mb_out      = out + (size_t)MAX_LEN * B;
    float* hidden      = mb_out + (size_t)MAX_LEN * B * D;
    float* lengths_out = hidden + (size_t)B * D;

    int* map = nullptr;
    cudaGetSymbolAddress((void**)&map, g_map);

    setup_kernel<<<64, 256>>>(src, lengths, recover, map, src_out,
                              hidden, lengths_out,
                              (int)B, (int)N, (int)NB, (int)MAX_LEN);

    const int grid = (int)((MAX_LEN + TC - 1) / TC);
    stream_kernel<<<grid, MAIN_T>>>(mb, map, lengths_out, mb_out, hidden,
                                    (int)B, (int)NB, (int)MAX_LEN);
}

// round 6
// speedup vs baseline: 1.3425x; 1.3425x over previous
#include <cuda_runtime.h>
#include <stdint.h>

// Ragged node-batch -> batch reconstruction, fused t-major streaming design.
// Inputs: src [L,NB], memory_bank [L,NB,D], lengths [NB], recover [NB]
// Output (flat): src_out [MAX_LEN,B], mb_out [MAX_LEN,B,D], hidden [B,D], lengths_out [B]
// Instance: B=32, N=64, L=128, D=256, NB=2048, MAX_LEN=8192.

#define MAXB   32
#define MAXN   64
#define TC     16            // t-rows per block
#define MAIN_T 512           // threads per block

__global__ void zero_hidden_kernel(float* __restrict__ hidden, int n4)
{
    int i = blockIdx.x * blockDim.x + threadIdx.x;
    if (i < n4)
        reinterpret_cast<float4*>(hidden)[i] = make_float4(0.f, 0.f, 0.f, 0.f);
}

// Block = t-chunk [t0, t0+TC) across ALL batches. 512 threads.
// Writes a contiguous TC*32KB span of mb_out; gathers scattered source rows.
__global__ void __launch_bounds__(MAIN_T, 3)
fused_kernel(const float* __restrict__ src,
             const float* __restrict__ mb,
             const int* __restrict__ lengths,
             const int* __restrict__ recover,
             float* __restrict__ src_out,
             float* __restrict__ mb_out,
             float* __restrict__ hidden,
             float* __restrict__ lengths_out,
             int B, int N, int D, int NB, int MAX_LEN)
{
    const int tid = threadIdx.x;
    const int t0  = blockIdx.x * TC;
    const int LANES = 64;                 // D/4
    const int rowF4 = B * LANES;          // 2048 float4 per t-row

    __shared__ int   s_incl[MAXB][MAXN + 1];  // padded: kills bank conflicts
    __shared__ int   s_map[TC * MAXB];        // mb row index or -1
    __shared__ float s_inv[MAXB];
    __shared__ int   s_lenb[MAXB];

    // ---- load lengths, per-batch inclusive prefix --------------------------
    for (int i = tid; i < B * N; i += MAIN_T)
        s_incl[i / MAXN][i % MAXN] = lengths[i];
    __syncthreads();
    if (tid < B) {
        int s = 0;
        #pragma unroll 8
        for (int i = 0; i < MAXN; ++i) { s += s_incl[tid][i]; s_incl[tid][i] = s; }
        s_lenb[tid] = s;
        s_inv[tid] = (s > 0) ? (1.0f / (float)s) : 0.0f;
    }
    __syncthreads();

    // ---- build map tile: s_map[tt*B + b] -----------------------------------
    for (int i = tid; i < TC * B; i += MAIN_T) {
        const int tt = i / B;
        const int b  = i - tt * B;
        const int t  = t0 + tt;
        int m = -1;
        if (t < s_lenb[b]) {
            int lo = 0, hi = N;
            while (lo < hi) {
                int mid = (lo + hi) >> 1;
                if (s_incl[b][mid] > t) hi = mid; else lo = mid + 1;
            }
            const int n   = lo;
            const int off = (n > 0) ? s_incl[b][n - 1] : 0;
            m = (t - off) * NB + b * N + n;   // p*NB + nb
        }
        s_map[i] = m;
    }
    __syncthreads();

    // ---- src_out slice -----------------------------------------------------
    for (int i = tid; i < TC * B; i += MAIN_T) {
        const int tt = i / B;
        const int b  = i - tt * B;
        const int m  = s_map[i];
        float val = 1.0f;
        if (m >= 0) {
            const int p  = m / NB;
            const int nb = m - p * NB;
            val = src[(size_t)p * NB + recover[nb]];
        }
        src_out[(size_t)(t0 + tt) * B + b] = val;
    }

    // ---- main copy: 4 (b,lane) chunks per thread ---------------------------
    const int bA = (0 * MAIN_T + tid) >> 6, lA = tid & 63;
    const int bB = (1 * MAIN_T + tid) >> 6;
    const int bC = (2 * MAIN_T + tid) >> 6;
    const int bD = (3 * MAIN_T + tid) >> 6;

    const float4* __restrict__ mb4 = reinterpret_cast<const float4*>(mb);
    float4* __restrict__ out4 =
        reinterpret_cast<float4*>(mb_out) + (size_t)t0 * rowF4;

    float4 acc0 = make_float4(0,0,0,0), acc1 = acc0, acc2 = acc0, acc3 = acc0;
    const float4 z4 = make_float4(0,0,0,0);

    #pragma unroll 2
    for (int tt = 0; tt < TC; ++tt) {
        const int* mrow = s_map + tt * B;
        const int m0 = mrow[bA];
        const int m1 = mrow[bB];
        const int m2 = mrow[bC];
        const int m3 = mrow[bD];
        float4 v0 = (m0 >= 0) ? mb4[(size_t)m0 * LANES + lA] : z4;
        float4 v1 = (m1 >= 0) ? mb4[(size_t)m1 * LANES + lA] : z4;
        float4 v2 = (m2 >= 0) ? mb4[(size_t)m2 * LANES + lA] : z4;
        float4 v3 = (m3 >= 0) ? mb4[(size_t)m3 * LANES + lA] : z4;
        float4* orow = out4 + (size_t)tt * rowF4 + tid;
        orow[0 * MAIN_T] = v0;
        orow[1 * MAIN_T] = v1;
        orow[2 * MAIN_T] = v2;
        orow[3 * MAIN_T] = v3;
        acc0.x += v0.x; acc0.y += v0.y; acc0.z += v0.z; acc0.w += v0.w;
        acc1.x += v1.x; acc1.y += v1.y; acc1.z += v1.z; acc1.w += v1.w;
        acc2.x += v2.x; acc2.y += v2.y; acc2.z += v2.z; acc2.w += v2.w;
        acc3.x += v3.x; acc3.y += v3.y; acc3.z += v3.z; acc3.w += v3.w;
    }

    // ---- hidden: vector red.global, only if this slab overlaps valid rows --
    if (t0 < s_lenb[bA]) {
        float i0 = s_inv[bA];
        float* h0 = hidden + bA * 256 + lA * 4;
        asm volatile("red.global.add.v4.f32 [%0], {%1,%2,%3,%4};" ::
            "l"(h0), "f"(acc0.x*i0), "f"(acc0.y*i0), "f"(acc0.z*i0), "f"(acc0.w*i0) : "memory");
    }
    if (t0 < s_lenb[bB]) {
        float i1 = s_inv[bB];
        float* h1 = hidden + bB * 256 + lA * 4;
        asm volatile("red.global.add.v4.f32 [%0], {%1,%2,%3,%4};" ::
            "l"(h1), "f"(acc1.x*i1), "f"(acc1.y*i1), "f"(acc1.z*i1), "f"(acc1.w*i1) : "memory");
    }
    if (t0 < s_lenb[bC]) {
        float i2 = s_inv[bC];
        float* h2 = hidden + bC * 256 + lA * 4;
        asm volatile("red.global.add.v4.f32 [%0], {%1,%2,%3,%4};" ::
            "l"(h2), "f"(acc2.x*i2), "f"(acc2.y*i2), "f"(acc2.z*i2), "f"(acc2.w*i2) : "memory");
    }
    if (t0 < s_lenb[bD]) {
        float i3 = s_inv[bD];
        float* h3 = hidden + bD * 256 + lA * 4;
        asm volatile("red.global.add.v4.f32 [%0], {%1,%2,%3,%4};" ::
            "l"(h3), "f"(acc3.x*i3), "f"(acc3.y*i3), "f"(acc3.z*i3), "f"(acc3.w*i3) : "memory");
    }

    if (blockIdx.x == 0 && tid < B)
        lengths_out[tid] = (float)s_lenb[tid];
}

extern "C" void kernel_launch(void* const* d_in, const int* in_sizes, int n_in,
                              void* d_out, int out_size)
{
    const float* src     = (const float*)d_in[0];
    const float* mb      = (const float*)d_in[1];
    const int*   lengths = (const int*)d_in[2];
    const int*   recover = (const int*)d_in[3];

    const long long NB = in_sizes[2];
    const long long L  = in_sizes[0] / NB;
    const long long D  = in_sizes[1] / in_sizes[0];
    const long long B  = (long long)out_size / (D + 1) - NB * L;
    const long long N  = NB / B;
    const long long MAX_LEN = N * L;

    float* out = (float*)d_out;
    float* src_out     = out;
    float* mb_out      = out + (size_t)MAX_LEN * B;
    float* hidden      = mb_out + (size_t)MAX_LEN * B * D;
    float* lengths_out = hidden + (size_t)B * D;

    {
        int n4 = (int)((B * D) / 4);
        zero_hidden_kernel<<<(n4 + 255) / 256, 256>>>(hidden, n4);
    }
    {
        const int grid = (int)(MAX_LEN / TC);
        fused_kernel<<<grid, MAIN_T>>>(src, mb, lengths, recover,
                                       src_out, mb_out, hidden, lengths_out,
                                       (int)B, (int)N, (int)D, (int)NB, (int)MAX_LEN);
    }
}